// round 3
// baseline (speedup 1.0000x reference)
#include <cuda_runtime.h>
#include <cuda_bf16.h>
#include <math.h>

// x, x_r : (1, 3, 32, 512, 512) fp32. hc=wc=32, 16x16 patches/frame, T=32.
// |(x+1)/2-(xr+1)/2| = |x-xr|/2. Patch elems = 3*32*32 = 3072.
//
// Block layout: one CTA per (frame t, patch-row ph) strip.
//   Strip = 32 rows x 512 cols x 3 channels  (3 x 64KB contiguous per tensor).
//   256 threads: col4 = tid & 127 (float4 col 0..127), rowgrp = tid >> 7 (0/1).
//   Each thread streams 16 rows (rowgrp*16 .. +16) over 3 channels = 48 float4
//   per tensor, all in the SAME spatial patch column pw = col4 >> 3.

#define T_FRAMES 32
#define NBLOCKS  (T_FRAMES * 16)     // 512

__device__ int g_frame_max[T_FRAMES] = {0};  // float bits; >= 0 so int atomicMax OK
__device__ unsigned g_done = 0;

__global__ __launch_bounds__(256) void patch_kernel(const float* __restrict__ x,
                                                    const float* __restrict__ xr,
                                                    float* __restrict__ out) {
    int b      = blockIdx.x;           // 0 .. 511
    int t      = b >> 4;               // frame
    int ph     = b & 15;               // patch row
    int tid    = threadIdx.x;
    int col4   = tid & 127;            // float4 column within 512-wide row
    int rowgrp = tid >> 7;             // 0 or 1 -> rows [rowgrp*16, rowgrp*16+16)

    float s = 0.0f;
    #pragma unroll
    for (int c = 0; c < 3; c++) {
        int base = (((c * T_FRAMES + t) * 512) + ph * 32 + rowgrp * 16) * 512 + col4 * 4;
        const float4* px = (const float4*)(x  + base);
        const float4* pr = (const float4*)(xr + base);
        #pragma unroll 4
        for (int r = 0; r < 16; r++) {
            float4 a  = __ldcs(px + r * 128);   // 128 float4 per 512-float row
            float4 rr = __ldcs(pr + r * 128);
            s += fabsf(a.x - rr.x) + fabsf(a.y - rr.y)
               + fabsf(a.z - rr.z) + fabsf(a.w - rr.w);
        }
    }

    // Reduce over the 8 lanes sharing a patch (col4 groups of 8)
    s += __shfl_xor_sync(0xffffffffu, s, 1);
    s += __shfl_xor_sync(0xffffffffu, s, 2);
    s += __shfl_xor_sync(0xffffffffu, s, 4);

    __shared__ float psum[16];
    if (tid < 16) psum[tid] = 0.0f;
    __syncthreads();
    if ((tid & 7) == 0) atomicAdd(&psum[col4 >> 3], s);   // 8 warps x 4 adds
    __syncthreads();

    if (tid < 32) {
        int lane = tid;
        // patch means for this strip; block max over 16 patches
        float pm = (lane < 16) ? psum[lane] * (1.0f / 6144.0f) : 0.0f;
        #pragma unroll
        for (int o = 8; o > 0; o >>= 1)
            pm = fmaxf(pm, __shfl_xor_sync(0xffffffffu, pm, o));

        bool last = false;
        if (lane == 0) {
            atomicMax(&g_frame_max[t], __float_as_int(pm));  // pm >= 0
            __threadfence();
            unsigned prev = atomicAdd(&g_done, 1u);
            last = (prev == NBLOCKS - 1);
        }
        last = __shfl_sync(0xffffffffu, (int)last, 0);

        if (last) {
            float fm = __int_as_float(g_frame_max[lane]);    // lane -> frame, >= 0
            float sum = fm;
            #pragma unroll
            for (int o = 16; o > 0; o >>= 1)
                sum += __shfl_xor_sync(0xffffffffu, sum, o);
            if (lane == 0) {
                out[0] = logf(sum * (1.0f / (float)T_FRAMES));
                g_done = 0;                                  // reset for next replay
            }
            g_frame_max[lane] = 0;                           // reset (and clamp at 0)
        }
    }
}

extern "C" void kernel_launch(void* const* d_in, const int* in_sizes, int n_in,
                              void* d_out, int out_size) {
    const float* x  = (const float*)d_in[0];
    const float* xr = (const float*)d_in[1];
    patch_kernel<<<NBLOCKS, 256>>>(x, xr, (float*)d_out);
}

// round 4
// speedup vs baseline: 1.0532x; 1.0532x over previous
#include <cuda_runtime.h>
#include <cuda_bf16.h>
#include <math.h>

// x, x_r : (1, 3, 32, 512, 512) fp32. hc=wc=32, 16x16 patches/frame, T=32.
// |(x+1)/2-(xr+1)/2| = |x-xr|/2. Patch elems = 3*32*32 = 3072 (= 768 float4).
// One block per patch, 128 threads, 6 float4 fragments per thread per tensor.

#define T_FRAMES 32
#define H_DIM    512
#define W_DIM    512
#define HC       32
#define WC       32
#define NBLOCKS  (T_FRAMES * 256)   // 8192

__device__ int g_frame_max[T_FRAMES] = {0};  // float bits; >= 0 so int atomicMax OK
__device__ unsigned g_done = 0;

__global__ __launch_bounds__(128) void patch_kernel(const float* __restrict__ x,
                                                    const float* __restrict__ xr,
                                                    float* __restrict__ out) {
    int b  = blockIdx.x;                  // 0 .. 8191
    int t  = b >> 8;                      // frame
    int p  = b & 255;                     // patch within frame
    int h0 = (p >> 4) * HC;
    int w0 = (p & 15) * WC;
    int tid = threadIdx.x;

    // Precompute 6 addresses; f = tid + 128*i spans [0,768).
    // col (f&7) is invariant across i; row/channel vary.
    const float4* ax[6];
    const float4* ar[6];
    #pragma unroll
    for (int i = 0; i < 6; i++) {
        int f   = tid + i * 128;
        int c   = f >> 8;                 // channel 0..2
        int rem = f & 255;
        int row = rem >> 3;               // 0..31
        int col = rem & 7;                // float4 col within patch
        int base = (((c * T_FRAMES + t) * H_DIM) + h0 + row) * W_DIM + w0 + (col << 2);
        ax[i] = (const float4*)(x  + base);
        ar[i] = (const float4*)(xr + base);
    }

    // Front-batched independent loads (12 LDG.128 in flight)
    float4 va[6], vr[6];
    #pragma unroll
    for (int i = 0; i < 6; i++) va[i] = __ldcs(ax[i]);
    #pragma unroll
    for (int i = 0; i < 6; i++) vr[i] = __ldcs(ar[i]);

    float s = 0.0f;
    #pragma unroll
    for (int i = 0; i < 6; i++) {
        s += fabsf(va[i].x - vr[i].x) + fabsf(va[i].y - vr[i].y)
           + fabsf(va[i].z - vr[i].z) + fabsf(va[i].w - vr[i].w);
    }

    // warp reduce
    #pragma unroll
    for (int o = 16; o > 0; o >>= 1)
        s += __shfl_xor_sync(0xffffffffu, s, o);

    __shared__ float warp_sums[4];
    int lane = tid & 31, wid = tid >> 5;
    if (lane == 0) warp_sums[wid] = s;
    __syncthreads();

    if (wid == 0) {
        float v = (lane < 4) ? warp_sums[lane] : 0.0f;
        v += __shfl_xor_sync(0xffffffffu, v, 1);
        v += __shfl_xor_sync(0xffffffffu, v, 2);

        bool last = false;
        if (lane == 0) {
            float pm = v * (1.0f / 6144.0f);          // /3072 (mean) and /2
            atomicMax(&g_frame_max[t], __float_as_int(pm));
            __threadfence();
            unsigned prev = atomicAdd(&g_done, 1u);
            last = (prev == NBLOCKS - 1);
        }
        last = __shfl_sync(0xffffffffu, (int)last, 0);

        if (last) {
            float fm = __int_as_float(g_frame_max[lane]);   // lane -> frame, >= 0
            float sum = fm;
            #pragma unroll
            for (int o = 16; o > 0; o >>= 1)
                sum += __shfl_xor_sync(0xffffffffu, sum, o);
            if (lane == 0) {
                out[0] = logf(sum * (1.0f / (float)T_FRAMES));
                g_done = 0;                                  // reset for next replay
            }
            g_frame_max[lane] = 0;                           // reset (and clamp at 0)
        }
    }
}

extern "C" void kernel_launch(void* const* d_in, const int* in_sizes, int n_in,
                              void* d_out, int out_size) {
    const float* x  = (const float*)d_in[0];
    const float* xr = (const float*)d_in[1];
    patch_kernel<<<NBLOCKS, 128>>>(x, xr, (float*)d_out);
}